// round 16
// baseline (speedup 1.0000x reference)
#include <cuda_runtime.h>
#include <cuda_fp16.h>
#include <math.h>
#include <stdint.h>

// ---------------------------------------------------------------------------
// InteractionBlock v16: v15 base + 1-MUFU polynomial softplus
// (exp2 MUFU + deg-5 minimax log1p in the FMA pipe; was ex2+lg2).
// ---------------------------------------------------------------------------

#define HF   128
#define MAXN 50000
#define MAXC 2048
#define TE   128
#define NTHR 256

__device__ __half g_hh[MAXN * HF];
__device__ float g_comp[MAXC * HF];
__device__ float g_cnt[MAXC];
__device__ int   g_node2comp[MAXN];

typedef unsigned int uint32;
typedef unsigned long long ull;

// ---- smem byte offsets for k_edge (total 70144 B/CTA -> 3 CTAs/SM) ----
#define OFF_AH  0          // fp16 [128 e][72 k] (stride 144B)     18432
#define OFF_W1F 18432      // frag w1 [16 jp][4 t][32 l][8B]       16384
#define OFF_W2F 34816      // frag w2 [16 nt][8 j][32 l][8B]       32768
#define OFF_B1  67584      // float[128]
#define OFF_B2  68096
#define OFF_SRC 68608      // int  [128]
#define OFF_CMP 69120
#define OFF_CV  69632
#define SMEM_E  70144

__device__ __forceinline__ float sspf(float x) {         // precise (tail)
    float ax = fabsf(x);
    return fmaxf(x, 0.0f) + log1pf(__expf(-ax)) - 0.6931471805599453f;
}
// 1-MUFU softplus: t = 2^(-|x|*log2e); log1p(t) by A&S 4.1.44 deg-5 (|e|<=1e-5)
__device__ __forceinline__ float sspf_fast(float x) {
    float ax = fabsf(x);
    float t;
    asm("ex2.approx.f32 %0, %1;" : "=f"(t) : "f"(-1.4426950408889634f * ax));
    float p = fmaf(t, 0.03215845f, -0.13606275f);
    p = fmaf(t, p, 0.28947478f);
    p = fmaf(t, p, -0.49190896f);
    p = fmaf(t, p, 0.99949556f);
    p = t * p;
    return fmaxf(x, 0.0f) + p - 0.6931471805599453f;
}
__device__ __forceinline__ uint32 packh2(float x0, float x1) {
    __half2 hh = __floats2half2_rn(x0, x1);
    return *reinterpret_cast<uint32*>(&hh);
}
__device__ __forceinline__ void ldmx4(uint32& r0, uint32& r1, uint32& r2, uint32& r3,
                                      uint32 saddr) {
    asm volatile("ldmatrix.sync.aligned.m8n8.x4.shared.b16 {%0,%1,%2,%3}, [%4];"
                 : "=r"(r0), "=r"(r1), "=r"(r2), "=r"(r3) : "r"(saddr));
}
__device__ __forceinline__ void mma16816(float& d0, float& d1, float& d2, float& d3,
                                         uint32 a0, uint32 a1, uint32 a2, uint32 a3,
                                         uint32 b0, uint32 b1) {
    asm volatile("mma.sync.aligned.m16n8k16.row.col.f32.f16.f16.f32 "
                 "{%0,%1,%2,%3},{%4,%5,%6,%7},{%8,%9},{%0,%1,%2,%3};"
                 : "+f"(d0), "+f"(d1), "+f"(d2), "+f"(d3)
                 : "r"(a0), "r"(a1), "r"(a2), "r"(a3), "r"(b0), "r"(b1));
}
__device__ __forceinline__ void redv4(float* p, float a, float b, float c, float d) {
    asm volatile("red.global.add.v4.f32 [%0], {%1,%2,%3,%4};"
                 :: "l"(p), "f"(a), "f"(b), "f"(c), "f"(d) : "memory");
}

// ---------------------------------------------------------------------------
__global__ void k_prep(const int* __restrict__ comp_member,
                       const int* __restrict__ comp_seg, int N) {
    int i = blockIdx.x * blockDim.x + threadIdx.x;
    if (i < N) {
        int node = comp_member[i];
        int c = comp_seg[i];
        g_node2comp[node] = c;
        atomicAdd(&g_cnt[c], 1.0f);
    }
}

// ---------------------------------------------------------------------------
// h = x @ lin1_w^T, stored as fp16
__global__ void __launch_bounds__(256) k_h(const float* __restrict__ x,
                                           const float* __restrict__ lin1_w,
                                           int N) {
    extern __shared__ float smf[];
    float* wT = smf;
    float* xs = smf + 128 * 129;
    int tid = threadIdx.x;

    for (int idx = tid; idx < 128 * 128; idx += 256) {
        int f = idx >> 7, k = idx & 127;
        wT[k * 129 + f] = lin1_w[idx];
    }
    int n0 = blockIdx.x * 64;
    for (int idx = tid; idx < 64 * 128; idx += 256) {
        int n = idx >> 7, k = idx & 127;
        int gn = n0 + n;
        xs[idx] = (gn < N) ? x[(size_t)gn * HF + k] : 0.0f;
    }
    __syncthreads();

    int f = tid & 127;
    int no = tid >> 7;
#pragma unroll
    for (int grp = 0; grp < 8; ++grp) {
        int e0 = no + 2 * (grp * 4);
        float a0 = 0.f, a1 = 0.f, a2 = 0.f, a3 = 0.f;
#pragma unroll 4
        for (int k4 = 0; k4 < 32; ++k4) {
            float w0 = wT[(4 * k4 + 0) * 129 + f];
            float w1 = wT[(4 * k4 + 1) * 129 + f];
            float w2 = wT[(4 * k4 + 2) * 129 + f];
            float w3 = wT[(4 * k4 + 3) * 129 + f];
            float4 v0 = *(const float4*)&xs[(e0    ) * 128 + 4 * k4];
            float4 v1 = *(const float4*)&xs[(e0 + 2) * 128 + 4 * k4];
            float4 v2 = *(const float4*)&xs[(e0 + 4) * 128 + 4 * k4];
            float4 v3 = *(const float4*)&xs[(e0 + 6) * 128 + 4 * k4];
            a0 = fmaf(v0.x, w0, a0); a0 = fmaf(v0.y, w1, a0);
            a0 = fmaf(v0.z, w2, a0); a0 = fmaf(v0.w, w3, a0);
            a1 = fmaf(v1.x, w0, a1); a1 = fmaf(v1.y, w1, a1);
            a1 = fmaf(v1.z, w2, a1); a1 = fmaf(v1.w, w3, a1);
            a2 = fmaf(v2.x, w0, a2); a2 = fmaf(v2.y, w1, a2);
            a2 = fmaf(v2.z, w2, a2); a2 = fmaf(v2.w, w3, a2);
            a3 = fmaf(v3.x, w0, a3); a3 = fmaf(v3.y, w1, a3);
            a3 = fmaf(v3.z, w2, a3); a3 = fmaf(v3.w, w3, a3);
        }
        int gn = n0 + e0;
        if (gn     < N) g_hh[(size_t)(gn    ) * HF + f] = __float2half_rn(a0);
        if (gn + 2 < N) g_hh[(size_t)(gn + 2) * HF + f] = __float2half_rn(a1);
        if (gn + 4 < N) g_hh[(size_t)(gn + 4) * HF + f] = __float2half_rn(a2);
        if (gn + 6 < N) g_hh[(size_t)(gn + 6) * HF + f] = __float2half_rn(a3);
    }
}

// ---------------------------------------------------------------------------
__global__ void __launch_bounds__(NTHR, 3) k_edge(
    const int* __restrict__ ei, const float* __restrict__ ew,
    const float* __restrict__ attr,
    const float* __restrict__ w1, const float* __restrict__ b1,
    const float* __restrict__ w2, const float* __restrict__ b2,
    int E) {
    extern __shared__ char sm[];
    float* b1s   = (float*)(sm + OFF_B1);
    float* b2s   = (float*)(sm + OFF_B2);
    int*   sSrc  = (int*)  (sm + OFF_SRC);
    int*   sCmp  = (int*)  (sm + OFF_CMP);
    float* sCv   = (float*)(sm + OFF_CV);
    uint32 sbase = (uint32)__cvta_generic_to_shared(sm);

    const int tid = threadIdx.x;
    const int w   = tid >> 5;
    const int l   = tid & 31;
    const int g   = l >> 2;
    const int q   = l & 3;

    // ---- one-time weight staging in FRAGMENT order (hi only, 8B/entry) ----
    for (int idx = tid; idx < 2048; idx += NTHR) {
        int lane = idx & 31, t = (idx >> 5) & 3, jp = idx >> 7;
        int gg = lane >> 2, qq = lane & 3;
        int n = 8 * jp + gg;
        int k0 = 16 * t + 2 * qq;
        int k1 = k0 + 8;
        float v00 = (k0     < 50) ? w1[n * 50 + k0]     : 0.0f;
        float v01 = (k0 + 1 < 50) ? w1[n * 50 + k0 + 1] : 0.0f;
        float v10 = (k1     < 50) ? w1[n * 50 + k1]     : 0.0f;
        float v11 = (k1 + 1 < 50) ? w1[n * 50 + k1 + 1] : 0.0f;
        uint2 f;
        f.x = packh2(v00, v01);
        f.y = packh2(v10, v11);
        *(uint2*)(sm + OFF_W1F + idx * 8) = f;
    }
    for (int idx = tid; idx < 4096; idx += NTHR) {
        int lane = idx & 31, j = (idx >> 5) & 7, nt = idx >> 8;
        int gg = lane >> 2, qq = lane & 3;
        int n = 8 * nt + gg;
        int k0 = 16 * j + 2 * qq;
        int k1 = k0 + 8;
        uint2 f;
        f.x = packh2(w2[n * 128 + k0], w2[n * 128 + k0 + 1]);
        f.y = packh2(w2[n * 128 + k1], w2[n * 128 + k1 + 1]);
        *(uint2*)(sm + OFF_W2F + idx * 8) = f;
    }
    if (tid < 128) { b1s[tid] = b1[tid]; b2s[tid] = b2[tid]; }
    // zero AH pad columns kp=25..31 once
    for (int idx = tid; idx < 128 * 7; idx += NTHR) {
        int row = idx / 7, kp = 25 + idx % 7;
        *(uint32*)(sm + OFF_AH + row * 144 + kp * 4) = 0;
    }

    const int numTiles = (E + TE - 1) / TE;

    for (int tile = blockIdx.x; tile < numTiles; tile += gridDim.x) {
        const int ebase = tile * TE;
        __syncthreads();   // prev tile's reads of AH/meta done

        // ---- metadata (direct LDG -> transform -> STS) ----
        if (tid < TE) {
            int ge = ebase + tid;
            int srcv = 0, compv = 0;
            float Cv = 0.0f;
            if (ge < E) {
                srcv = ei[ge];
                compv = g_node2comp[ei[E + ge]];
                float wv = ew[ge];
                Cv = 10.0f / (1e-10f + wv * wv) - 1.0f;
            }
            sSrc[tid] = srcv;
            sCmp[tid] = compv;
            sCv [tid] = Cv;
        }
        // ---- attr convert: direct LDG.64 -> packh2 -> STS (kp 0..24) ----
        for (int i = tid; i < TE * 25; i += NTHR) {
            int e = i / 25, ch = i - e * 25;
            int ge = ebase + e;
            uint32 v = 0;
            if (ge < E) {
                float2 a = *(const float2*)(attr + (size_t)ge * 50 + 2 * ch);
                v = packh2(a.x, a.y);
            }
            *(uint32*)(sm + OFF_AH + e * 144 + ch * 4) = v;
        }
        __syncthreads();   // AH + meta visible

        // ---- stage-1 A fragments ----
        uint32 ahf[4][4];
        {
            uint32 arow = sbase + OFF_AH + (16 * w + (l & 15)) * 144 + ((l >> 4) * 16);
#pragma unroll
            for (int t = 0; t < 4; ++t)
                ldmx4(ahf[t][0], ahf[t][1], ahf[t][2], ahf[t][3], arow + t * 32);
        }

        // ---- stage 1: hidden fragments ua[8][4] ----
        uint32 ua[8][4];
#pragma unroll
        for (int j = 0; j < 8; ++j) {
            float a1[2][4];
#pragma unroll
            for (int p = 0; p < 2; ++p) {
                float2 bb = *(const float2*)&b1s[16 * j + 8 * p + 2 * q];
                a1[p][0] = bb.x; a1[p][1] = bb.y;
                a1[p][2] = bb.x; a1[p][3] = bb.y;
            }
#pragma unroll
            for (int t = 0; t < 4; ++t) {
#pragma unroll
                for (int p = 0; p < 2; ++p) {
                    uint2 f = *(const uint2*)(sm + OFF_W1F
                              + ((2 * j + p) * 4 + t) * 256 + l * 8);
                    mma16816(a1[p][0], a1[p][1], a1[p][2], a1[p][3],
                             ahf[t][0], ahf[t][1], ahf[t][2], ahf[t][3], f.x, f.y);
                }
            }
            ua[j][0] = packh2(sspf_fast(a1[0][0]), sspf_fast(a1[0][1]));
            ua[j][1] = packh2(sspf_fast(a1[0][2]), sspf_fast(a1[0][3]));
            ua[j][2] = packh2(sspf_fast(a1[1][0]), sspf_fast(a1[1][1]));
            ua[j][3] = packh2(sspf_fast(a1[1][2]), sspf_fast(a1[1][3]));
        }

        // ---- stream stage 2 + epilogue, n-tile PAIRS, even/odd-j split ----
        const int rowe = g + ((q & 1) << 3);
        const int eIdx = 16 * w + rowe;
        const float Cv = sCv[eIdx];
        const __half* hrow = g_hh + (size_t)sSrc[eIdx] * HF;
        float* crow = &g_comp[sCmp[eIdx] * HF];
        const bool doit = (Cv != 0.0f);
        const int podd = q & 1;
        const int p4 = (q >> 1) << 2;

#pragma unroll
        for (int ntp = 0; ntp < 8; ++ntp) {
            const int ntA = 2 * ntp, ntB = 2 * ntp + 1;
            int colA = 8 * ntA + p4, colB = 8 * ntB + p4;
            uint2 hvA = __ldg((const uint2*)(hrow + colA));
            uint2 hvB = __ldg((const uint2*)(hrow + colB));

            float ae0, ae1, ae2, ae3, ao0, ao1, ao2, ao3;
            float be0, be1, be2, be3, bo0, bo1, bo2, bo3;
            {
                float2 bb = *(const float2*)&b2s[8 * ntA + 2 * q];
                ae0 = bb.x; ae1 = bb.y; ae2 = bb.x; ae3 = bb.y;
            }
            {
                float2 bb = *(const float2*)&b2s[8 * ntB + 2 * q];
                be0 = bb.x; be1 = bb.y; be2 = bb.x; be3 = bb.y;
            }
            ao0 = ao1 = ao2 = ao3 = 0.0f;
            bo0 = bo1 = bo2 = bo3 = 0.0f;
#pragma unroll
            for (int jj = 0; jj < 4; ++jj) {
                int je = 2 * jj, jo = 2 * jj + 1;
                uint2 fae = *(const uint2*)(sm + OFF_W2F + (ntA * 8 + je) * 256 + l * 8);
                uint2 fao = *(const uint2*)(sm + OFF_W2F + (ntA * 8 + jo) * 256 + l * 8);
                uint2 fbe = *(const uint2*)(sm + OFF_W2F + (ntB * 8 + je) * 256 + l * 8);
                uint2 fbo = *(const uint2*)(sm + OFF_W2F + (ntB * 8 + jo) * 256 + l * 8);
                mma16816(ae0, ae1, ae2, ae3,
                         ua[je][0], ua[je][1], ua[je][2], ua[je][3], fae.x, fae.y);
                mma16816(ao0, ao1, ao2, ao3,
                         ua[jo][0], ua[jo][1], ua[jo][2], ua[jo][3], fao.x, fao.y);
                mma16816(be0, be1, be2, be3,
                         ua[je][0], ua[je][1], ua[je][2], ua[je][3], fbe.x, fbe.y);
                mma16816(bo0, bo1, bo2, bo3,
                         ua[jo][0], ua[jo][1], ua[jo][2], ua[jo][3], fbo.x, fbo.y);
            }
            float dA0 = ae0 + ao0, dA1 = ae1 + ao1, dA2 = ae2 + ao2, dA3 = ae3 + ao3;
            float dB0 = be0 + bo0, dB1 = be1 + bo1, dB2 = be2 + bo2, dB3 = be3 + bo3;

            {
                ull send;
                if (podd) { asm("mov.b64 %0,{%1,%2};" : "=l"(send) : "f"(dA0), "f"(dA1)); }
                else      { asm("mov.b64 %0,{%1,%2};" : "=l"(send) : "f"(dA2), "f"(dA3)); }
                ull rcv = __shfl_xor_sync(0xffffffffu, send, 1);
                float rx, ry;
                asm("mov.b64 {%0,%1},%2;" : "=f"(rx), "=f"(ry) : "l"(rcv));
                float v0, v1, v2, v3;
                if (podd) { v0 = rx; v1 = ry; v2 = dA2; v3 = dA3; }
                else      { v0 = dA0; v1 = dA1; v2 = rx; v3 = ry; }
                if (doit) {
                    float2 f0 = __half22float2(*(__half2*)&hvA.x);
                    float2 f1 = __half22float2(*(__half2*)&hvA.y);
                    v0 *= Cv * f0.x; v1 *= Cv * f0.y;
                    v2 *= Cv * f1.x; v3 *= Cv * f1.y;
                    redv4(crow + colA, v0, v1, v2, v3);
                }
            }
            {
                ull send;
                if (podd) { asm("mov.b64 %0,{%1,%2};" : "=l"(send) : "f"(dB0), "f"(dB1)); }
                else      { asm("mov.b64 %0,{%1,%2};" : "=l"(send) : "f"(dB2), "f"(dB3)); }
                ull rcv = __shfl_xor_sync(0xffffffffu, send, 1);
                float rx, ry;
                asm("mov.b64 {%0,%1},%2;" : "=f"(rx), "=f"(ry) : "l"(rcv));
                float v0, v1, v2, v3;
                if (podd) { v0 = rx; v1 = ry; v2 = dB2; v3 = dB3; }
                else      { v0 = dB0; v1 = dB1; v2 = rx; v3 = ry; }
                if (doit) {
                    float2 f0 = __half22float2(*(__half2*)&hvB.x);
                    float2 f1 = __half22float2(*(__half2*)&hvB.y);
                    v0 *= Cv * f0.x; v1 *= Cv * f0.y;
                    v2 *= Cv * f1.x; v3 *= Cv * f1.y;
                    redv4(crow + colB, v0, v1, v2, v3);
                }
            }
        }
    }
}

// ---------------------------------------------------------------------------
// Tail: mean -> lin2 -> ssp -> lin (unchanged)
__global__ void __launch_bounds__(256) k_final(
    const float* __restrict__ lin2_w, const float* __restrict__ lin2_b,
    const float* __restrict__ lin_w,  const float* __restrict__ lin_b,
    float* __restrict__ out) {
    __shared__ float sin_[16 * 128];
    __shared__ float sy[16 * 128];
    __shared__ float swT[32 * 129];
    int tid = threadIdx.x;
    int c0 = blockIdx.x * 16;

    for (int idx = tid; idx < 2048; idx += 256) {
        int c = idx >> 7;
        float cnt = g_cnt[c0 + c];
        sin_[idx] = g_comp[(c0 + c) * HF + (idx & 127)] / fmaxf(cnt, 1.0f);
    }
    __syncthreads();

    int f  = tid & 127;
    int co = tid >> 7;
    float acc[8];
#pragma unroll
    for (int j = 0; j < 8; ++j) acc[j] = lin2_b[f];
    for (int kb = 0; kb < 4; ++kb) {
        __syncthreads();
        for (int idx = tid; idx < 4096; idx += 256) {
            int f_ = idx >> 5, kk = idx & 31;
            swT[kk * 129 + f_] = lin2_w[f_ * 128 + kb * 32 + kk];
        }
        __syncthreads();
        for (int kk = 0; kk < 32; ++kk) {
            float wv = swT[kk * 129 + f];
#pragma unroll
            for (int j = 0; j < 8; ++j)
                acc[j] = fmaf(sin_[(co + 2 * j) * 128 + kb * 32 + kk], wv, acc[j]);
        }
    }
#pragma unroll
    for (int j = 0; j < 8; ++j)
        sy[(co + 2 * j) * 128 + f] = sspf(acc[j]);

    float acc2[8];
#pragma unroll
    for (int j = 0; j < 8; ++j) acc2[j] = lin_b[f];
    for (int kb = 0; kb < 4; ++kb) {
        __syncthreads();
        for (int idx = tid; idx < 4096; idx += 256) {
            int f_ = idx >> 5, kk = idx & 31;
            swT[kk * 129 + f_] = lin_w[f_ * 128 + kb * 32 + kk];
        }
        __syncthreads();
        for (int kk = 0; kk < 32; ++kk) {
            float wv = swT[kk * 129 + f];
#pragma unroll
            for (int j = 0; j < 8; ++j)
                acc2[j] = fmaf(sy[(co + 2 * j) * 128 + kb * 32 + kk], wv, acc2[j]);
        }
    }
#pragma unroll
    for (int j = 0; j < 8; ++j)
        out[(size_t)(c0 + co + 2 * j) * HF + f] = acc2[j];
}

// ---------------------------------------------------------------------------
extern "C" void kernel_launch(void* const* d_in, const int* in_sizes, int n_in,
                              void* d_out, int out_size) {
    const float* x        = (const float*)d_in[0];
    const int*   ei       = (const int*)  d_in[1];
    const float* ew       = (const float*)d_in[2];
    const float* attr     = (const float*)d_in[3];
    const int*   cmember  = (const int*)  d_in[4];
    const int*   cseg     = (const int*)  d_in[5];
    const float* mlp_w1   = (const float*)d_in[6];
    const float* mlp_b1   = (const float*)d_in[7];
    const float* mlp_w2   = (const float*)d_in[8];
    const float* mlp_b2   = (const float*)d_in[9];
    const float* lin1_w   = (const float*)d_in[10];
    const float* lin2_w   = (const float*)d_in[11];
    const float* lin2_b   = (const float*)d_in[12];
    const float* lin_w    = (const float*)d_in[13];
    const float* lin_b    = (const float*)d_in[14];
    float* out = (float*)d_out;

    int N = in_sizes[0] / HF;
    int E = in_sizes[2];
    int NC = out_size / HF;

    void *p_comp, *p_cnt;
    cudaGetSymbolAddress(&p_comp, g_comp);
    cudaGetSymbolAddress(&p_cnt, g_cnt);
    cudaMemsetAsync(p_comp, 0, (size_t)NC * HF * sizeof(float));
    cudaMemsetAsync(p_cnt, 0, (size_t)NC * sizeof(float));

    int sms = 148;
    int dev = 0;
    cudaGetDevice(&dev);
    cudaDeviceGetAttribute(&sms, cudaDevAttrMultiProcessorCount, dev);

    const int SMEM_H = (128 * 129 + 64 * 128) * 4;
    cudaFuncSetAttribute(k_h, cudaFuncAttributeMaxDynamicSharedMemorySize, SMEM_H);
    cudaFuncSetAttribute(k_edge, cudaFuncAttributeMaxDynamicSharedMemorySize, SMEM_E);

    int numTiles = (E + TE - 1) / TE;
    int grid = 3 * sms < numTiles ? 3 * sms : numTiles;

    k_prep<<<(N + 255) / 256, 256>>>(cmember, cseg, N);
    k_h<<<(N + 63) / 64, 256, SMEM_H>>>(x, lin1_w, N);
    k_edge<<<grid, NTHR, SMEM_E>>>(ei, ew, attr, mlp_w1, mlp_b1,
                                   mlp_w2, mlp_b2, E);
    k_final<<<NC / 16, 256>>>(lin2_w, lin2_b, lin_w, lin_b, out);
}

// round 17
// speedup vs baseline: 1.0957x; 1.0957x over previous
#include <cuda_runtime.h>
#include <cuda_fp16.h>
#include <math.h>
#include <stdint.h>

// ---------------------------------------------------------------------------
// InteractionBlock v17: v15 k_edge (best) + merged prep-into-k_h + FFMA2 k_h.
// ---------------------------------------------------------------------------

#define HF   128
#define MAXN 50000
#define MAXC 2048
#define TE   128
#define NTHR 256

__device__ __half g_hh[MAXN * HF];
__device__ float g_comp[MAXC * HF];
__device__ float g_cnt[MAXC];
__device__ int   g_node2comp[MAXN];

typedef unsigned int uint32;
typedef unsigned long long ull;

// ---- smem byte offsets for k_edge (total 70144 B/CTA -> 3 CTAs/SM) ----
#define OFF_AH  0
#define OFF_W1F 18432
#define OFF_W2F 34816
#define OFF_B1  67584
#define OFF_B2  68096
#define OFF_SRC 68608
#define OFF_CMP 69120
#define OFF_CV  69632
#define SMEM_E  70144

__device__ __forceinline__ float sspf(float x) {
    float ax = fabsf(x);
    return fmaxf(x, 0.0f) + log1pf(__expf(-ax)) - 0.6931471805599453f;
}
__device__ __forceinline__ float sspf_fast(float x) {    // v15 version (2 MUFU)
    float ax = fabsf(x);
    return fmaxf(x, 0.0f) + __logf(1.0f + __expf(-ax)) - 0.6931471805599453f;
}
__device__ __forceinline__ uint32 packh2(float x0, float x1) {
    __half2 hh = __floats2half2_rn(x0, x1);
    return *reinterpret_cast<uint32*>(&hh);
}
__device__ __forceinline__ ull fma2(ull a, ull b, ull c) {
    ull d;
    asm("fma.rn.f32x2 %0, %1, %2, %3;" : "=l"(d) : "l"(a), "l"(b), "l"(c));
    return d;
}
__device__ __forceinline__ ull splat2(float x) {
    unsigned u = __float_as_uint(x);
    ull d;
    asm("mov.b64 %0, {%1, %1};" : "=l"(d) : "r"(u));
    return d;
}
__device__ __forceinline__ float2 unpack2(ull v) {
    unsigned lo, hi;
    asm("mov.b64 {%0, %1}, %2;" : "=r"(lo), "=r"(hi) : "l"(v));
    return make_float2(__uint_as_float(lo), __uint_as_float(hi));
}
__device__ __forceinline__ void ldmx4(uint32& r0, uint32& r1, uint32& r2, uint32& r3,
                                      uint32 saddr) {
    asm volatile("ldmatrix.sync.aligned.m8n8.x4.shared.b16 {%0,%1,%2,%3}, [%4];"
                 : "=r"(r0), "=r"(r1), "=r"(r2), "=r"(r3) : "r"(saddr));
}
__device__ __forceinline__ void mma16816(float& d0, float& d1, float& d2, float& d3,
                                         uint32 a0, uint32 a1, uint32 a2, uint32 a3,
                                         uint32 b0, uint32 b1) {
    asm volatile("mma.sync.aligned.m16n8k16.row.col.f32.f16.f16.f32 "
                 "{%0,%1,%2,%3},{%4,%5,%6,%7},{%8,%9},{%0,%1,%2,%3};"
                 : "+f"(d0), "+f"(d1), "+f"(d2), "+f"(d3)
                 : "r"(a0), "r"(a1), "r"(a2), "r"(a3), "r"(b0), "r"(b1));
}
__device__ __forceinline__ void redv4(float* p, float a, float b, float c, float d) {
    asm volatile("red.global.add.v4.f32 [%0], {%1,%2,%3,%4};"
                 :: "l"(p), "f"(a), "f"(b), "f"(c), "f"(d) : "memory");
}

// ---------------------------------------------------------------------------
// Fused: node->comp map + counts (first 64 threads of each block, same node
// range) AND h = x @ lin1_w^T via packed f32x2 FMA, stored fp16.
// smem: wP ull[128][65] (66560 B) + xs float[64][128] (32768 B) = 99328 B
__global__ void __launch_bounds__(256) k_h(const float* __restrict__ x,
                                           const float* __restrict__ lin1_w,
                                           const int* __restrict__ comp_member,
                                           const int* __restrict__ comp_seg,
                                           int N) {
    extern __shared__ char smc[];
    ull*   wP  = (ull*)smc;                    // [k][fp] stride 65
    float* wPf = (float*)smc;
    float* xs  = (float*)(smc + 128 * 65 * 8);
    int tid = threadIdx.x;
    int n0 = blockIdx.x * 64;

    // ---- fused prep: this block's 64 nodes ----
    if (tid < 64) {
        int i = n0 + tid;
        if (i < N) {
            int node = comp_member[i];
            int c = comp_seg[i];
            g_node2comp[node] = c;
            atomicAdd(&g_cnt[c], 1.0f);
        }
    }

    // ---- stage weights into packed [k][fpair] layout ----
    for (int idx = tid; idx < 128 * 128; idx += 256) {
        int f = idx >> 7, k = idx & 127;
        wPf[(k * 65 + (f >> 1)) * 2 + (f & 1)] = lin1_w[idx];
    }
    for (int idx = tid; idx < 64 * 128; idx += 256) {
        int n = idx >> 7, k = idx & 127;
        int gn = n0 + n;
        xs[idx] = (gn < N) ? x[(size_t)gn * HF + k] : 0.0f;
    }
    __syncthreads();

    const int fp = tid & 63;        // f-pair: covers f = 2fp, 2fp+1
    const int no = tid >> 6;        // 0..3
    ull acc[16];
#pragma unroll
    for (int i = 0; i < 16; ++i) acc[i] = 0;

    for (int k4 = 0; k4 < 32; ++k4) {
        ull w0 = wP[(4 * k4 + 0) * 65 + fp];
        ull w1 = wP[(4 * k4 + 1) * 65 + fp];
        ull w2 = wP[(4 * k4 + 2) * 65 + fp];
        ull w3 = wP[(4 * k4 + 3) * 65 + fp];
#pragma unroll
        for (int i = 0; i < 16; ++i) {
            int e = no + 4 * i;
            float4 v = *(const float4*)&xs[e * 128 + 4 * k4];
            acc[i] = fma2(splat2(v.x), w0, acc[i]);
            acc[i] = fma2(splat2(v.y), w1, acc[i]);
            acc[i] = fma2(splat2(v.z), w2, acc[i]);
            acc[i] = fma2(splat2(v.w), w3, acc[i]);
        }
    }
#pragma unroll
    for (int i = 0; i < 16; ++i) {
        int gn = n0 + no + 4 * i;
        if (gn < N) {
            float2 r = unpack2(acc[i]);
            *(uint32*)&g_hh[(size_t)gn * HF + 2 * fp] = packh2(r.x, r.y);
        }
    }
}

// ---------------------------------------------------------------------------
// k_edge: byte-identical to v15
__global__ void __launch_bounds__(NTHR, 3) k_edge(
    const int* __restrict__ ei, const float* __restrict__ ew,
    const float* __restrict__ attr,
    const float* __restrict__ w1, const float* __restrict__ b1,
    const float* __restrict__ w2, const float* __restrict__ b2,
    int E) {
    extern __shared__ char sm[];
    float* b1s   = (float*)(sm + OFF_B1);
    float* b2s   = (float*)(sm + OFF_B2);
    int*   sSrc  = (int*)  (sm + OFF_SRC);
    int*   sCmp  = (int*)  (sm + OFF_CMP);
    float* sCv   = (float*)(sm + OFF_CV);
    uint32 sbase = (uint32)__cvta_generic_to_shared(sm);

    const int tid = threadIdx.x;
    const int w   = tid >> 5;
    const int l   = tid & 31;
    const int g   = l >> 2;
    const int q   = l & 3;

    for (int idx = tid; idx < 2048; idx += NTHR) {
        int lane = idx & 31, t = (idx >> 5) & 3, jp = idx >> 7;
        int gg = lane >> 2, qq = lane & 3;
        int n = 8 * jp + gg;
        int k0 = 16 * t + 2 * qq;
        int k1 = k0 + 8;
        float v00 = (k0     < 50) ? w1[n * 50 + k0]     : 0.0f;
        float v01 = (k0 + 1 < 50) ? w1[n * 50 + k0 + 1] : 0.0f;
        float v10 = (k1     < 50) ? w1[n * 50 + k1]     : 0.0f;
        float v11 = (k1 + 1 < 50) ? w1[n * 50 + k1 + 1] : 0.0f;
        uint2 f;
        f.x = packh2(v00, v01);
        f.y = packh2(v10, v11);
        *(uint2*)(sm + OFF_W1F + idx * 8) = f;
    }
    for (int idx = tid; idx < 4096; idx += NTHR) {
        int lane = idx & 31, j = (idx >> 5) & 7, nt = idx >> 8;
        int gg = lane >> 2, qq = lane & 3;
        int n = 8 * nt + gg;
        int k0 = 16 * j + 2 * qq;
        int k1 = k0 + 8;
        uint2 f;
        f.x = packh2(w2[n * 128 + k0], w2[n * 128 + k0 + 1]);
        f.y = packh2(w2[n * 128 + k1], w2[n * 128 + k1 + 1]);
        *(uint2*)(sm + OFF_W2F + idx * 8) = f;
    }
    if (tid < 128) { b1s[tid] = b1[tid]; b2s[tid] = b2[tid]; }
    for (int idx = tid; idx < 128 * 7; idx += NTHR) {
        int row = idx / 7, kp = 25 + idx % 7;
        *(uint32*)(sm + OFF_AH + row * 144 + kp * 4) = 0;
    }

    const int numTiles = (E + TE - 1) / TE;

    for (int tile = blockIdx.x; tile < numTiles; tile += gridDim.x) {
        const int ebase = tile * TE;
        __syncthreads();

        if (tid < TE) {
            int ge = ebase + tid;
            int srcv = 0, compv = 0;
            float Cv = 0.0f;
            if (ge < E) {
                srcv = ei[ge];
                compv = g_node2comp[ei[E + ge]];
                float wv = ew[ge];
                Cv = 10.0f / (1e-10f + wv * wv) - 1.0f;
            }
            sSrc[tid] = srcv;
            sCmp[tid] = compv;
            sCv [tid] = Cv;
        }
        for (int i = tid; i < TE * 25; i += NTHR) {
            int e = i / 25, ch = i - e * 25;
            int ge = ebase + e;
            uint32 v = 0;
            if (ge < E) {
                float2 a = *(const float2*)(attr + (size_t)ge * 50 + 2 * ch);
                v = packh2(a.x, a.y);
            }
            *(uint32*)(sm + OFF_AH + e * 144 + ch * 4) = v;
        }
        __syncthreads();

        uint32 ahf[4][4];
        {
            uint32 arow = sbase + OFF_AH + (16 * w + (l & 15)) * 144 + ((l >> 4) * 16);
#pragma unroll
            for (int t = 0; t < 4; ++t)
                ldmx4(ahf[t][0], ahf[t][1], ahf[t][2], ahf[t][3], arow + t * 32);
        }

        uint32 ua[8][4];
#pragma unroll
        for (int j = 0; j < 8; ++j) {
            float a1[2][4];
#pragma unroll
            for (int p = 0; p < 2; ++p) {
                float2 bb = *(const float2*)&b1s[16 * j + 8 * p + 2 * q];
                a1[p][0] = bb.x; a1[p][1] = bb.y;
                a1[p][2] = bb.x; a1[p][3] = bb.y;
            }
#pragma unroll
            for (int t = 0; t < 4; ++t) {
#pragma unroll
                for (int p = 0; p < 2; ++p) {
                    uint2 f = *(const uint2*)(sm + OFF_W1F
                              + ((2 * j + p) * 4 + t) * 256 + l * 8);
                    mma16816(a1[p][0], a1[p][1], a1[p][2], a1[p][3],
                             ahf[t][0], ahf[t][1], ahf[t][2], ahf[t][3], f.x, f.y);
                }
            }
            ua[j][0] = packh2(sspf_fast(a1[0][0]), sspf_fast(a1[0][1]));
            ua[j][1] = packh2(sspf_fast(a1[0][2]), sspf_fast(a1[0][3]));
            ua[j][2] = packh2(sspf_fast(a1[1][0]), sspf_fast(a1[1][1]));
            ua[j][3] = packh2(sspf_fast(a1[1][2]), sspf_fast(a1[1][3]));
        }

        const int rowe = g + ((q & 1) << 3);
        const int eIdx = 16 * w + rowe;
        const float Cv = sCv[eIdx];
        const __half* hrow = g_hh + (size_t)sSrc[eIdx] * HF;
        float* crow = &g_comp[sCmp[eIdx] * HF];
        const bool doit = (Cv != 0.0f);
        const int podd = q & 1;
        const int p4 = (q >> 1) << 2;

#pragma unroll
        for (int ntp = 0; ntp < 8; ++ntp) {
            const int ntA = 2 * ntp, ntB = 2 * ntp + 1;
            int colA = 8 * ntA + p4, colB = 8 * ntB + p4;
            uint2 hvA = __ldg((const uint2*)(hrow + colA));
            uint2 hvB = __ldg((const uint2*)(hrow + colB));

            float ae0, ae1, ae2, ae3, ao0, ao1, ao2, ao3;
            float be0, be1, be2, be3, bo0, bo1, bo2, bo3;
            {
                float2 bb = *(const float2*)&b2s[8 * ntA + 2 * q];
                ae0 = bb.x; ae1 = bb.y; ae2 = bb.x; ae3 = bb.y;
            }
            {
                float2 bb = *(const float2*)&b2s[8 * ntB + 2 * q];
                be0 = bb.x; be1 = bb.y; be2 = bb.x; be3 = bb.y;
            }
            ao0 = ao1 = ao2 = ao3 = 0.0f;
            bo0 = bo1 = bo2 = bo3 = 0.0f;
#pragma unroll
            for (int jj = 0; jj < 4; ++jj) {
                int je = 2 * jj, jo = 2 * jj + 1;
                uint2 fae = *(const uint2*)(sm + OFF_W2F + (ntA * 8 + je) * 256 + l * 8);
                uint2 fao = *(const uint2*)(sm + OFF_W2F + (ntA * 8 + jo) * 256 + l * 8);
                uint2 fbe = *(const uint2*)(sm + OFF_W2F + (ntB * 8 + je) * 256 + l * 8);
                uint2 fbo = *(const uint2*)(sm + OFF_W2F + (ntB * 8 + jo) * 256 + l * 8);
                mma16816(ae0, ae1, ae2, ae3,
                         ua[je][0], ua[je][1], ua[je][2], ua[je][3], fae.x, fae.y);
                mma16816(ao0, ao1, ao2, ao3,
                         ua[jo][0], ua[jo][1], ua[jo][2], ua[jo][3], fao.x, fao.y);
                mma16816(be0, be1, be2, be3,
                         ua[je][0], ua[je][1], ua[je][2], ua[je][3], fbe.x, fbe.y);
                mma16816(bo0, bo1, bo2, bo3,
                         ua[jo][0], ua[jo][1], ua[jo][2], ua[jo][3], fbo.x, fbo.y);
            }
            float dA0 = ae0 + ao0, dA1 = ae1 + ao1, dA2 = ae2 + ao2, dA3 = ae3 + ao3;
            float dB0 = be0 + bo0, dB1 = be1 + bo1, dB2 = be2 + bo2, dB3 = be3 + bo3;

            {
                ull send;
                if (podd) { asm("mov.b64 %0,{%1,%2};" : "=l"(send) : "f"(dA0), "f"(dA1)); }
                else      { asm("mov.b64 %0,{%1,%2};" : "=l"(send) : "f"(dA2), "f"(dA3)); }
                ull rcv = __shfl_xor_sync(0xffffffffu, send, 1);
                float rx, ry;
                asm("mov.b64 {%0,%1},%2;" : "=f"(rx), "=f"(ry) : "l"(rcv));
                float v0, v1, v2, v3;
                if (podd) { v0 = rx; v1 = ry; v2 = dA2; v3 = dA3; }
                else      { v0 = dA0; v1 = dA1; v2 = rx; v3 = ry; }
                if (doit) {
                    float2 f0 = __half22float2(*(__half2*)&hvA.x);
                    float2 f1 = __half22float2(*(__half2*)&hvA.y);
                    v0 *= Cv * f0.x; v1 *= Cv * f0.y;
                    v2 *= Cv * f1.x; v3 *= Cv * f1.y;
                    redv4(crow + colA, v0, v1, v2, v3);
                }
            }
            {
                ull send;
                if (podd) { asm("mov.b64 %0,{%1,%2};" : "=l"(send) : "f"(dB0), "f"(dB1)); }
                else      { asm("mov.b64 %0,{%1,%2};" : "=l"(send) : "f"(dB2), "f"(dB3)); }
                ull rcv = __shfl_xor_sync(0xffffffffu, send, 1);
                float rx, ry;
                asm("mov.b64 {%0,%1},%2;" : "=f"(rx), "=f"(ry) : "l"(rcv));
                float v0, v1, v2, v3;
                if (podd) { v0 = rx; v1 = ry; v2 = dB2; v3 = dB3; }
                else      { v0 = dB0; v1 = dB1; v2 = rx; v3 = ry; }
                if (doit) {
                    float2 f0 = __half22float2(*(__half2*)&hvB.x);
                    float2 f1 = __half22float2(*(__half2*)&hvB.y);
                    v0 *= Cv * f0.x; v1 *= Cv * f0.y;
                    v2 *= Cv * f1.x; v3 *= Cv * f1.y;
                    redv4(crow + colB, v0, v1, v2, v3);
                }
            }
        }
    }
}

// ---------------------------------------------------------------------------
// Tail: mean -> lin2 -> ssp -> lin (unchanged)
__global__ void __launch_bounds__(256) k_final(
    const float* __restrict__ lin2_w, const float* __restrict__ lin2_b,
    const float* __restrict__ lin_w,  const float* __restrict__ lin_b,
    float* __restrict__ out) {
    __shared__ float sin_[16 * 128];
    __shared__ float sy[16 * 128];
    __shared__ float swT[32 * 129];
    int tid = threadIdx.x;
    int c0 = blockIdx.x * 16;

    for (int idx = tid; idx < 2048; idx += 256) {
        int c = idx >> 7;
        float cnt = g_cnt[c0 + c];
        sin_[idx] = g_comp[(c0 + c) * HF + (idx & 127)] / fmaxf(cnt, 1.0f);
    }
    __syncthreads();

    int f  = tid & 127;
    int co = tid >> 7;
    float acc[8];
#pragma unroll
    for (int j = 0; j < 8; ++j) acc[j] = lin2_b[f];
    for (int kb = 0; kb < 4; ++kb) {
        __syncthreads();
        for (int idx = tid; idx < 4096; idx += 256) {
            int f_ = idx >> 5, kk = idx & 31;
            swT[kk * 129 + f_] = lin2_w[f_ * 128 + kb * 32 + kk];
        }
        __syncthreads();
        for (int kk = 0; kk < 32; ++kk) {
            float wv = swT[kk * 129 + f];
#pragma unroll
            for (int j = 0; j < 8; ++j)
                acc[j] = fmaf(sin_[(co + 2 * j) * 128 + kb * 32 + kk], wv, acc[j]);
        }
    }
#pragma unroll
    for (int j = 0; j < 8; ++j)
        sy[(co + 2 * j) * 128 + f] = sspf(acc[j]);

    float acc2[8];
#pragma unroll
    for (int j = 0; j < 8; ++j) acc2[j] = lin_b[f];
    for (int kb = 0; kb < 4; ++kb) {
        __syncthreads();
        for (int idx = tid; idx < 4096; idx += 256) {
            int f_ = idx >> 5, kk = idx & 31;
            swT[kk * 129 + f_] = lin_w[f_ * 128 + kb * 32 + kk];
        }
        __syncthreads();
        for (int kk = 0; kk < 32; ++kk) {
            float wv = swT[kk * 129 + f];
#pragma unroll
            for (int j = 0; j < 8; ++j)
                acc2[j] = fmaf(sy[(co + 2 * j) * 128 + kb * 32 + kk], wv, acc2[j]);
        }
    }
#pragma unroll
    for (int j = 0; j < 8; ++j)
        out[(size_t)(c0 + co + 2 * j) * HF + f] = acc2[j];
}

// ---------------------------------------------------------------------------
extern "C" void kernel_launch(void* const* d_in, const int* in_sizes, int n_in,
                              void* d_out, int out_size) {
    const float* x        = (const float*)d_in[0];
    const int*   ei       = (const int*)  d_in[1];
    const float* ew       = (const float*)d_in[2];
    const float* attr     = (const float*)d_in[3];
    const int*   cmember  = (const int*)  d_in[4];
    const int*   cseg     = (const int*)  d_in[5];
    const float* mlp_w1   = (const float*)d_in[6];
    const float* mlp_b1   = (const float*)d_in[7];
    const float* mlp_w2   = (const float*)d_in[8];
    const float* mlp_b2   = (const float*)d_in[9];
    const float* lin1_w   = (const float*)d_in[10];
    const float* lin2_w   = (const float*)d_in[11];
    const float* lin2_b   = (const float*)d_in[12];
    const float* lin_w    = (const float*)d_in[13];
    const float* lin_b    = (const float*)d_in[14];
    float* out = (float*)d_out;

    int N = in_sizes[0] / HF;
    int E = in_sizes[2];
    int NC = out_size / HF;

    void *p_comp, *p_cnt;
    cudaGetSymbolAddress(&p_comp, g_comp);
    cudaGetSymbolAddress(&p_cnt, g_cnt);
    cudaMemsetAsync(p_comp, 0, (size_t)NC * HF * sizeof(float));
    cudaMemsetAsync(p_cnt, 0, (size_t)NC * sizeof(float));

    int sms = 148;
    int dev = 0;
    cudaGetDevice(&dev);
    cudaDeviceGetAttribute(&sms, cudaDevAttrMultiProcessorCount, dev);

    const int SMEM_H = 128 * 65 * 8 + 64 * 128 * 4;   // 99328
    cudaFuncSetAttribute(k_h, cudaFuncAttributeMaxDynamicSharedMemorySize, SMEM_H);
    cudaFuncSetAttribute(k_edge, cudaFuncAttributeMaxDynamicSharedMemorySize, SMEM_E);

    int numTiles = (E + TE - 1) / TE;
    int grid = 3 * sms < numTiles ? 3 * sms : numTiles;

    k_h<<<(N + 63) / 64, 256, SMEM_H>>>(x, lin1_w, cmember, cseg, N);
    k_edge<<<grid, NTHR, SMEM_E>>>(ei, ew, attr, mlp_w1, mlp_b1,
                                   mlp_w2, mlp_b2, E);
    k_final<<<NC / 16, 256>>>(lin2_w, lin2_b, lin_w, lin_b, out);
}